// round 17
// baseline (speedup 1.0000x reference)
#include <cuda_runtime.h>
#include <cstdint>

#define HID 2048
#define SEQ 2048
#define BATCH 2
#define NH 16
#define HD 128
#define MTOT (BATCH*SEQ)   /* 4096 */
#define HID2 (HID/2)

// ---------------- scratch (no allocations allowed) ----------------
__device__ uint32_t g_Hp[MTOT*HID2];     // hidden, f16x2 K-paired, [M][K/2]
__device__ uint32_t g_WqT[HID*HID2];     // Wq^T: [N][K/2] f16x2 K-contiguous
__device__ uint32_t g_WoT[HID*HID2];
__device__ uint32_t g_WkT[HD*HID2];      // [128][1024]
__device__ uint32_t g_WvT[HD*HID2];
__device__ uint32_t g_Qp[MTOT*HID2];     // Q f16x2 d-paired, scale folded
__device__ uint32_t g_Kp[MTOT*(HD/2)];   // K f16x2 d-paired
__device__ uint32_t g_Vd[MTOT*(HD/2)];   // V f16x2 d-paired
__device__ uint32_t g_Vk[(MTOT/2)*HD];   // V f16x2 key-paired
__device__ uint32_t g_Ap[MTOT*HID2];     // attn out, f16x2 K-paired [M][K/2]

// ---------------- numeric helpers ----------------
__device__ __forceinline__ uint32_t pack_h2(float lo, float hi) {
    uint32_t r; asm("cvt.rn.f16x2.f32 %0, %1, %2;" : "=r"(r) : "f"(hi), "f"(lo)); return r;
}
__device__ __forceinline__ void mma16f(float* d, const uint32_t* a, uint32_t b0, uint32_t b1) {
    asm volatile(
        "mma.sync.aligned.m16n8k16.row.col.f32.f16.f16.f32 "
        "{%0,%1,%2,%3}, {%4,%5,%6,%7}, {%8,%9}, {%0,%1,%2,%3};"
        : "+f"(d[0]), "+f"(d[1]), "+f"(d[2]), "+f"(d[3])
        : "r"(a[0]), "r"(a[1]), "r"(a[2]), "r"(a[3]), "r"(b0), "r"(b1));
}
__device__ __forceinline__ void ldsm4(uint32_t addr, uint32_t* r) {
    asm volatile("ldmatrix.sync.aligned.m8n8.x4.shared.b16 {%0,%1,%2,%3}, [%4];"
        : "=r"(r[0]), "=r"(r[1]), "=r"(r[2]), "=r"(r[3]) : "r"(addr));
}
__device__ __forceinline__ uint32_t s2u(const void* p) {
    return (uint32_t)__cvta_generic_to_shared(p);
}
__device__ __forceinline__ void cp16(uint32_t dst, const void* src) {
    asm volatile("cp.async.cg.shared.global [%0], [%1], 16;" :: "r"(dst), "l"(src));
}
#define CP_COMMIT  asm volatile("cp.async.commit_group;" ::: "memory")
#define CP_WAIT(n) asm volatile("cp.async.wait_group %0;" :: "n"(n) : "memory")

// ---------------- one-time pack: hidden K-paired; weights TRANSPOSED ----------------
__global__ void pack_all(
    const float* __restrict__ H,  const float* __restrict__ Wq,
    const float* __restrict__ Wk, const float* __restrict__ Wv,
    const float* __restrict__ Wo,
    uint32_t* __restrict__ Hp,  uint32_t* __restrict__ WqT,
    uint32_t* __restrict__ WkT, uint32_t* __restrict__ WvT,
    uint32_t* __restrict__ WoT)
{
    int i = blockIdx.x * 256 + threadIdx.x;
    const int nH = MTOT * HID2, nQ = HID * HID2, nK = HD * HID2;
    if (i < nH) {
        float2 v = ((const float2*)H)[i];
        Hp[i] = pack_h2(v.x, v.y);
    } else if ((i -= nH) < nQ) {
        int n = i / HID2, kp = i - n * HID2;    // write-coalesced
        WqT[i] = pack_h2(Wq[(size_t)(2 * kp) * HID + n], Wq[(size_t)(2 * kp + 1) * HID + n]);
    } else if ((i -= nQ) < nK) {
        int n = i / HID2, kp = i - n * HID2;
        WkT[i] = pack_h2(Wk[(size_t)(2 * kp) * HD + n], Wk[(size_t)(2 * kp + 1) * HD + n]);
    } else if ((i -= nK) < nK) {
        int n = i / HID2, kp = i - n * HID2;
        WvT[i] = pack_h2(Wv[(size_t)(2 * kp) * HD + n], Wv[(size_t)(2 * kp + 1) * HD + n]);
    } else if ((i -= nK) < nQ) {
        int n = i / HID2, kp = i - n * HID2;
        WoT[i] = pack_h2(Wo[(size_t)(2 * kp) * HID + n], Wo[(size_t)(2 * kp + 1) * HID + n]);
    }
}

// V repack: d-paired [seq][HD/2] -> key-paired [seq/2][HD]
__global__ void repackV(const uint32_t* __restrict__ Vd, uint32_t* __restrict__ Vk)
{
    int i = blockIdx.x * 256 + threadIdx.x;
    if (i >= (MTOT / 2) * (HD / 2)) return;
    int kp = i >> 6, j = i & 63;
    uint32_t a = Vd[(size_t)(2 * kp) * 64 + j];
    uint32_t b = Vd[(size_t)(2 * kp + 1) * 64 + j];
    Vk[(size_t)kp * HD + 2 * j]     = __byte_perm(a, b, 0x5410);
    Vk[(size_t)kp * HD + 2 * j + 1] = __byte_perm(a, b, 0x7632);
}

// ======================================================================
// fp16 GEMM with ldmatrix fragments: C[M,N] = A[M,K] @ B^T (B n-major).
// 512 threads / 16 warps, block tile (128*MT) x 128, BK=32.
// A smem [BM][16] u32 stride 20; B smem [128][16] u32 stride 20; both
// LDSM-friendly (rows = m/n, 8-f16 k-groups contiguous, conflict-free).
// 6 LDSM + 32 HMMA per warp-iter (was 48 LDS.32 + 32 HMMA).
// TFOUT=0: C float (+bias). TFOUT=1: C u32 f16x2 of (acc+bias)*prescale.
// gridDim.z selects operand set 0/1 (fused K/V projection).
// ======================================================================
#define SA 20
#define SB 20
#define GEMM_SMEM(MT) ((2*(128*(MT))*SA + 2*128*SB) * 4)   /* MT=2: 61440 B */

template<int MT, int TFOUT>
__global__ __launch_bounds__(512) void gemm_f16(
    const uint32_t* __restrict__ Ap,
    const uint32_t* __restrict__ Bt0, const float* __restrict__ bias0, void* __restrict__ C0,
    const uint32_t* __restrict__ Bt1, const float* __restrict__ bias1, void* __restrict__ C1,
    int N, int K, float prescale)
{
    constexpr int BM   = 128 * MT;
    constexpr int ASTG = BM * SA;
    constexpr int BSTG = 128 * SB;

    extern __shared__ uint32_t smg[];
    uint32_t* sA = smg;                  // 2 x ASTG
    uint32_t* sB = sA + 2*ASTG;          // 2 x BSTG
    const uint32_t aA = s2u(sA), aB = s2u(sB);

    const uint32_t* Bt   = blockIdx.z ? Bt1   : Bt0;
    const float*    bias = blockIdx.z ? bias1 : bias0;
    void*           C    = blockIdx.z ? C1    : C0;

    const int tid  = threadIdx.x;
    const int lane = tid & 31, wid = tid >> 5;
    const int g = lane >> 2, t = lane & 3;
    const int wm = (wid >> 1) * (16 * MT);
    const int wn = (wid & 1) * 64;
    const int row0 = blockIdx.y * BM;
    const int col0 = blockIdx.x * 128;
    const int K2 = K >> 1;

    // ldmatrix per-lane tile/row assignment
    const int Lrow = lane & 7, Lt = lane >> 3;      // tile 0..3
    const int arow = (Lt & 1) * 8 + Lrow, acol = (Lt >> 1) * 4;
    const int brow = (Lt >> 1) * 8 + Lrow, bcol = (Lt & 1) * 4;

    float acc[MT][8][4];
    #pragma unroll
    for (int i = 0; i < MT; i++)
        #pragma unroll
        for (int j = 0; j < 8; j++)
            #pragma unroll
            for (int c = 0; c < 4; c++) acc[i][j][c] = 0.f;

    auto load_stage = [&](int kp0, int st) {
        // A: BM rows x 16 u32 -> BM*4 chunks
        #pragma unroll
        for (int j = 0; j < MT; j++) {
            int idx = tid + j * 512;
            int r = idx >> 2, c = (idx & 3) * 4;
            cp16(aA + (uint32_t)(st * ASTG + r * SA + c) * 4,
                 Ap + (size_t)(row0 + r) * K2 + kp0 + c);
        }
        // B: 128 n-rows x 16 u32 -> 512 chunks
        {
            int r = tid >> 2, c = (tid & 3) * 4;
            cp16(aB + (uint32_t)(st * BSTG + r * SB + c) * 4,
                 Bt + (size_t)(col0 + r) * K2 + kp0 + c);
        }
    };

    const int NIT = K / 32;              // 16 packed rows per iter
    load_stage(0, 0); CP_COMMIT;

    for (int it = 0; it < NIT; ++it) {
        const int st = it & 1;
        if (it + 1 < NIT) { load_stage((it + 1) * 16, st ^ 1); CP_COMMIT; CP_WAIT(1); }
        else              { CP_WAIT(0); }
        __syncthreads();

        const uint32_t baseA = aA + (uint32_t)(st * ASTG) * 4;
        const uint32_t baseB = aB + (uint32_t)(st * BSTG) * 4;

        #pragma unroll
        for (int s = 0; s < 2; s++) {            // two k16 steps per BK=32
            const int kb = s * 8;
            uint32_t ah[MT][4];
            #pragma unroll
            for (int mt = 0; mt < MT; mt++)
                ldsm4(baseA + (uint32_t)((wm + mt * 16 + arow) * SA + kb + acol) * 4, ah[mt]);
            uint32_t bb[8][2];
            #pragma unroll
            for (int ntp = 0; ntp < 4; ntp++) {
                uint32_t r[4];
                ldsm4(baseB + (uint32_t)((wn + ntp * 16 + brow) * SB + kb + bcol) * 4, r);
                bb[2*ntp][0] = r[0]; bb[2*ntp][1] = r[1];
                bb[2*ntp+1][0] = r[2]; bb[2*ntp+1][1] = r[3];
            }
            #pragma unroll
            for (int nt = 0; nt < 8; nt++)
                #pragma unroll
                for (int mt = 0; mt < MT; mt++)
                    mma16f(acc[mt][nt], ah[mt], bb[nt][0], bb[nt][1]);
        }
        __syncthreads();
    }

    #pragma unroll
    for (int mt = 0; mt < MT; mt++) {
        int row = row0 + wm + mt * 16 + g;
        #pragma unroll
        for (int nt = 0; nt < 8; nt++) {
            int col = col0 + wn + nt * 8 + 2 * t;
            float bx = bias[col], by = bias[col + 1];
            float v00 = acc[mt][nt][0] + bx, v01 = acc[mt][nt][1] + by;
            float v10 = acc[mt][nt][2] + bx, v11 = acc[mt][nt][3] + by;
            if (TFOUT) {
                uint32_t* Cu = (uint32_t*)C;
                int N2 = N >> 1;
                Cu[(size_t)row * N2 + (col >> 1)]       = pack_h2(v00 * prescale, v01 * prescale);
                Cu[(size_t)(row + 8) * N2 + (col >> 1)] = pack_h2(v10 * prescale, v11 * prescale);
            } else {
                float* Cf = (float*)C;
                *(float2*)(Cf + (size_t)row * N + col)       = make_float2(v00, v01);
                *(float2*)(Cf + (size_t)(row + 8) * N + col) = make_float2(v10, v11);
            }
        }
    }
}

// ======================================================================
// Flash attention, fp16 m16n8k16, 256 thr / 8 warps (R15-proven, unchanged).
// ======================================================================
#define SQ2 68
#define SK2 68
#define SV2 136
#define ATTN_SMEM ((128*SQ2 + 2*64*SK2 + 2*32*SV2) * 4)   /* 104448 B */

__global__ __launch_bounds__(256) void attn_f16(
    const uint32_t* __restrict__ Qp, const uint32_t* __restrict__ Kp,
    const uint32_t* __restrict__ Vk,
    uint32_t* __restrict__ OutP)
{
    extern __shared__ uint32_t sm[];
    uint32_t* Qs = sm;
    uint32_t* Ks = Qs + 128 * SQ2;
    uint32_t* Vs = Ks + 2 * 64 * SK2;
    const uint32_t aQ = s2u(Qs), aK = s2u(Ks), aV = s2u(Vs);

    const int tid  = threadIdx.x;
    const int lane = tid & 31, warp = tid >> 5;
    const int g = lane >> 2, t = lane & 3;
    const int qt = blockIdx.x, h = blockIdx.y, b = blockIdx.z;

    const size_t qrow0 = (size_t)(b * SEQ + qt * 128);

    auto load_K = [&](int tile, int st) {
        #pragma unroll
        for (int j = 0; j < 4; j++) {
            int idx = tid + j * 256;
            int r = idx >> 4, c = (idx & 15) * 4;
            cp16(aK + (uint32_t)(st * 64 * SK2 + r * SK2 + c) * 4,
                 Kp + ((size_t)(b * SEQ + tile * 64 + r)) * 64 + c);
        }
    };
    auto load_V = [&](int tile, int st) {
        #pragma unroll
        for (int j = 0; j < 4; j++) {
            int idx = tid + j * 256;
            int r = idx >> 5, c = (idx & 31) * 4;
            cp16(aV + (uint32_t)(st * 32 * SV2 + r * SV2 + c) * 4,
                 Vk + ((size_t)(b * (SEQ / 2) + tile * 32 + r)) * HD + c);
        }
    };

    #pragma unroll
    for (int j = 0; j < 8; j++) {
        int idx = tid + j * 256;
        int r = idx >> 4, c = (idx & 15) * 4;
        cp16(aQ + (uint32_t)(r * SQ2 + c) * 4,
             Qp + (qrow0 + r) * HID2 + h * 64 + c);
    }
    load_K(0, 0);
    load_V(0, 0);
    CP_COMMIT;

    float mrow[2] = { -1e30f, -1e30f };
    float lrow[2] = { 0.f, 0.f };
    float o[16][4];
    #pragma unroll
    for (int nt = 0; nt < 16; nt++)
        #pragma unroll
        for (int c = 0; c < 4; c++) o[nt][c] = 0.f;

    const int r0 = warp * 16 + g, r1 = r0 + 8;
    const int NT = SEQ / 64;

    for (int kt = 0; kt < NT; kt++) {
        CP_WAIT(0);
        __syncthreads();
        if (kt + 1 < NT) {
            load_K(kt + 1, (kt + 1) & 1);
            load_V(kt + 1, (kt + 1) & 1);
            CP_COMMIT;
        }

        const uint32_t* Kst = Ks + (kt & 1) * 64 * SK2;
        const uint32_t* Vst = Vs + (kt & 1) * 32 * SV2;

        float s[8][4];
        #pragma unroll
        for (int nt = 0; nt < 8; nt++)
            #pragma unroll
            for (int c = 0; c < 4; c++) s[nt][c] = 0.f;

        #pragma unroll
        for (int c = 0; c < 8; c++) {
            const int kb = c * 8;
            uint32_t a[4];
            a[0] = Qs[r0 * SQ2 + kb + t];
            a[1] = Qs[r1 * SQ2 + kb + t];
            a[2] = Qs[r0 * SQ2 + kb + t + 4];
            a[3] = Qs[r1 * SQ2 + kb + t + 4];
            #pragma unroll
            for (int nt = 0; nt < 8; nt++) {
                int cn = nt * 8 + g;
                uint32_t b0 = Kst[cn * SK2 + kb + t];
                uint32_t b1 = Kst[cn * SK2 + kb + t + 4];
                mma16f(s[nt], a, b0, b1);
            }
        }

        float tm0 = -1e30f, tm1 = -1e30f;
        #pragma unroll
        for (int nt = 0; nt < 8; nt++) {
            tm0 = fmaxf(tm0, fmaxf(s[nt][0], s[nt][1]));
            tm1 = fmaxf(tm1, fmaxf(s[nt][2], s[nt][3]));
        }
        tm0 = fmaxf(tm0, __shfl_xor_sync(0xffffffffu, tm0, 1));
        tm0 = fmaxf(tm0, __shfl_xor_sync(0xffffffffu, tm0, 2));
        tm1 = fmaxf(tm1, __shfl_xor_sync(0xffffffffu, tm1, 1));
        tm1 = fmaxf(tm1, __shfl_xor_sync(0xffffffffu, tm1, 2));

        float mn0 = fmaxf(mrow[0], tm0), mn1 = fmaxf(mrow[1], tm1);
        float f0 = __expf(mrow[0] - mn0), f1 = __expf(mrow[1] - mn1);
        mrow[0] = mn0; mrow[1] = mn1;
        lrow[0] *= f0; lrow[1] *= f1;
        #pragma unroll
        for (int nt = 0; nt < 16; nt++) {
            o[nt][0] *= f0; o[nt][1] *= f0;
            o[nt][2] *= f1; o[nt][3] *= f1;
        }

        uint32_t pp[8][2];
        float ps0 = 0.f, ps1 = 0.f;
        #pragma unroll
        for (int nt = 0; nt < 8; nt++) {
            float p0 = __expf(s[nt][0] - mn0); ps0 += p0;
            float p1 = __expf(s[nt][1] - mn0); ps0 += p1;
            float p2 = __expf(s[nt][2] - mn1); ps1 += p2;
            float p3 = __expf(s[nt][3] - mn1); ps1 += p3;
            pp[nt][0] = pack_h2(p0, p1);
            pp[nt][1] = pack_h2(p2, p3);
        }
        ps0 += __shfl_xor_sync(0xffffffffu, ps0, 1);
        ps0 += __shfl_xor_sync(0xffffffffu, ps0, 2);
        ps1 += __shfl_xor_sync(0xffffffffu, ps1, 1);
        ps1 += __shfl_xor_sync(0xffffffffu, ps1, 2);
        lrow[0] += ps0; lrow[1] += ps1;

        #pragma unroll
        for (int c = 0; c < 4; c++) {
            uint32_t a[4] = { pp[2*c][0], pp[2*c][1], pp[2*c+1][0], pp[2*c+1][1] };
            const int kb = c * 8;
            #pragma unroll
            for (int nt = 0; nt < 16; nt++) {
                int cn = nt * 8 + g;
                uint32_t b0 = Vst[(kb + t) * SV2 + cn];
                uint32_t b1 = Vst[(kb + t + 4) * SV2 + cn];
                mma16f(o[nt], a, b0, b1);
            }
        }
    }

    float inv0 = 1.f / lrow[0], inv1 = 1.f / lrow[1];
    const size_t obp = (qrow0 + r0) * HID2 + h * (HD / 2);
    #pragma unroll
    for (int nt = 0; nt < 16; nt++) {
        int cp = nt * 4 + t;
        OutP[obp + cp]            = pack_h2(o[nt][0] * inv0, o[nt][1] * inv0);
        OutP[obp + 8 * HID2 + cp] = pack_h2(o[nt][2] * inv1, o[nt][3] * inv1);
    }
}

// ---------------- launch ----------------
extern "C" void kernel_launch(void* const* d_in, const int* in_sizes, int n_in,
                              void* d_out, int out_size)
{
    const float* hidden = (const float*)d_in[0];
    const float* Wq = (const float*)d_in[1];
    const float* bq = (const float*)d_in[2];
    const float* Wk = (const float*)d_in[3];
    const float* bk = (const float*)d_in[4];
    const float* Wv = (const float*)d_in[5];
    const float* bv = (const float*)d_in[6];
    const float* Wo = (const float*)d_in[7];
    const float* bo = (const float*)d_in[8];
    float* out = (float*)d_out;

    uint32_t *Hp, *WqT, *WkT, *WvT, *WoT;
    uint32_t *Qpp, *Kpp, *Vdp, *Vkp, *App;
    cudaGetSymbolAddress((void**)&Hp,  g_Hp);
    cudaGetSymbolAddress((void**)&WqT, g_WqT);
    cudaGetSymbolAddress((void**)&WkT, g_WkT);
    cudaGetSymbolAddress((void**)&WvT, g_WvT);
    cudaGetSymbolAddress((void**)&WoT, g_WoT);
    cudaGetSymbolAddress((void**)&Qpp, g_Qp);
    cudaGetSymbolAddress((void**)&Kpp, g_Kp);
    cudaGetSymbolAddress((void**)&Vdp, g_Vd);
    cudaGetSymbolAddress((void**)&Vkp, g_Vk);
    cudaGetSymbolAddress((void**)&App, g_Ap);

    cudaFuncSetAttribute(gemm_f16<1,1>, cudaFuncAttributeMaxDynamicSharedMemorySize, GEMM_SMEM(1));
    cudaFuncSetAttribute(gemm_f16<2,1>, cudaFuncAttributeMaxDynamicSharedMemorySize, GEMM_SMEM(2));
    cudaFuncSetAttribute(gemm_f16<2,0>, cudaFuncAttributeMaxDynamicSharedMemorySize, GEMM_SMEM(2));
    cudaFuncSetAttribute(attn_f16,      cudaFuncAttributeMaxDynamicSharedMemorySize, ATTN_SMEM);

    const float scale = 0.08838834764831845f;   // 1/sqrt(128)

    // one-time packs (single launch)
    {
        int total = MTOT*HID2 + 2*(HID*HID2) + 2*(HD*HID2);
        pack_all<<<(total + 255)/256, 256>>>(hidden, Wq, Wk, Wv, Wo,
                                             Hp, WqT, WkT, WvT, WoT);
    }
    // K / V projections fused (f16x2 out), N=128, BM=128
    {
        dim3 grid(1, MTOT / 128, 2);
        gemm_f16<1,1><<<grid, 512, GEMM_SMEM(1)>>>(Hp,
                                                   WkT, bk, Kpp,
                                                   WvT, bv, Vdp,
                                                   HD, HID, 1.0f);
    }
    // V repack: d-pairs -> key-pairs
    {
        int total = (MTOT / 2) * (HD / 2);
        repackV<<<(total + 255)/256, 256>>>(Vdp, Vkp);
    }
    // Q projection (f16x2 out, scale folded), BM=256
    {
        dim3 grid(HID / 128, MTOT / 256, 1);
        gemm_f16<2,1><<<grid, 512, GEMM_SMEM(2)>>>(Hp,
                                                   WqT, bq, Qpp,
                                                   WqT, bq, Qpp,
                                                   HID, HID, scale);
    }
    // attention (fp16 mma, register-resident P)
    {
        dim3 grid(SEQ / 128, NH, BATCH);
        attn_f16<<<grid, 256, ATTN_SMEM>>>(Qpp, Kpp, Vkp, App);
    }
    // O projection (fp32 out) -> d_out, BM=256
    {
        dim3 grid(HID / 128, MTOT / 256, 1);
        gemm_f16<2,0><<<grid, 512, GEMM_SMEM(2)>>>(App,
                                                   WoT, bo, out,
                                                   WoT, bo, out,
                                                   HID, HID, 1.0f);
    }
}